// round 4
// baseline (speedup 1.0000x reference)
#include <cuda_runtime.h>

#define HH 480
#define WW 640
#define NC 3
#define SKIP 5
#define PH 96            // HH/SKIP
#define PW 128           // WW/SKIP
#define NP (PH*PW)       // 12288 sampled pixels
#define BH 60            // bin rows   (GRID=8, start 4)
#define BWID 80          // bin cols
#define NB (BH*BWID)     // 4800 bins
#define BPT 4            // bins per thread (same bin row)
#define CPG (BWID/BPT)   // 20 col-groups per bin row
#define NTH (BH*CPG)     // 1200 worker threads (bin side)
#define BGRID 5          // 5*256 = 1280 threads >= 1200
#define PSPLIT 59        // pixel-slice CTAs
#define TOTAL_CTAS (BGRID*PSPLIT)   // 295

// ---------- device scratch (zero-initialized at module load) ----------
__device__ float g_px[2*NP];   // NEGATED px
__device__ float g_py[2*NP];   // NEGATED py
__device__ float g_ux[2*NP];   // 2*ux
__device__ float g_uy[2*NP];   // 2*uy
__device__ float g_dd[2*NP];   // dist
__device__ int   g_n[2];       // compacted counts (class 1,2) -- reset by epilogue
__device__ int   g_cnt[NC];    // raw label counts             -- reset by epilogue
__device__ int   g_done;       // CTA completion counter       -- reset by epilogue
__device__ float g_dsum[2*NB];
__device__ float g_rois_scratch[NC*6];
__device__ float g_hough_scratch[NC*NB];

// ---------- packed f32x2 helpers ----------
typedef unsigned long long u64;
__device__ __forceinline__ u64 add2(u64 a, u64 b) {
    u64 d; asm("add.rn.f32x2 %0, %1, %2;" : "=l"(d) : "l"(a), "l"(b)); return d;
}
__device__ __forceinline__ u64 mul2(u64 a, u64 b) {
    u64 d; asm("mul.rn.f32x2 %0, %1, %2;" : "=l"(d) : "l"(a), "l"(b)); return d;
}
__device__ __forceinline__ u64 fma2(u64 a, u64 b, u64 c) {
    u64 d; asm("fma.rn.f32x2 %0, %1, %2, %3;" : "=l"(d) : "l"(a), "l"(b), "l"(c)); return d;
}
__device__ __forceinline__ u64 pack2(float lo, float hi) {
    u64 d; asm("mov.b64 %0, {%1, %2};" : "=l"(d) : "f"(lo), "f"(hi)); return d;
}
__device__ __forceinline__ void unpack2(u64 x, float& lo, float& hi) {
    asm("mov.b64 {%0, %1}, %2;" : "=f"(lo), "=f"(hi) : "l"(x));
}

// ---------- kernel 1: zero accumulators + gather/compact sampled pixels ----------
#define PREP_TH (NC*NB)   // 14400 >= NP
__global__ void prep_k(const int* __restrict__ label,
                       const float* __restrict__ vert,
                       float* __restrict__ hough) {
    int i = blockIdx.x * blockDim.x + threadIdx.x;
    if (i < NC*NB) hough[i] = 0.0f;
    if (i < 2*NB)  g_dsum[i] = 0.0f;

    if (i >= NP) return;
    int r = i / PW, c = i % PW;
    int vy = r * SKIP, vx = c * SKIP;
    int vl = label[vy * WW + vx];
    atomicAdd(&g_cnt[vl], 1);
    if (vl > 0) {
        int seg  = vl - 1;
        int slot = atomicAdd(&g_n[seg], 1) + seg * NP;
        int base = (vl * 3) * (HH * WW) + vy * WW + vx;
        g_px[slot] = -(float)vx;
        g_py[slot] = -(float)vy;
        g_ux[slot] = 2.0f * vert[base];
        g_uy[slot] = 2.0f * vert[base + HH * WW];
        g_dd[slot] = vert[base + 2 * HH * WW];
    }
}

// ---------- kernel 2: pairwise voting + fused epilogue ----------
__global__ void __launch_bounds__(256, 2)
vote_k(float* __restrict__ hough,
       float* __restrict__ rois,
       const float* __restrict__ meta,
       const float* __restrict__ extents) {
    __shared__ __align__(16) float s_px[258];
    __shared__ __align__(16) float s_py[258];
    __shared__ __align__(16) float s_ux[258];
    __shared__ __align__(16) float s_uy[258];
    __shared__ __align__(16) float s_dd[258];
    __shared__ float sv[256];
    __shared__ int   si[256];
    __shared__ int   s_last;

    int tid = threadIdx.x;
    int gt  = blockIdx.x * 256 + tid;
    bool active = gt < NTH;
    int binrow = gt / CPG;
    int colg   = gt % CPG;
    float byf  = 4.0f + 8.0f * (float)binrow;
    float bx0  = 4.0f + 8.0f * (float)(colg * BPT);
    u64 byf2   = pack2(byf, byf);
    u64 bx02   = pack2(bx0, bx0);
    u64 eps2   = pack2(1e-6f, 1e-6f);
    u64 eight2 = pack2(8.0f, 8.0f);

    for (int seg = 0; seg < 2; seg++) {
        int n     = g_n[seg];
        int chunk = (n + PSPLIT - 1) / PSPLIT;
        int start = blockIdx.y * chunk;
        int end   = min(start + chunk, n);

        int   cH[BPT] = {0, 0, 0, 0};
        float aD[BPT] = {0.f, 0.f, 0.f, 0.f};

        for (int t = start; t < end; t += 256) {
            int m = min(256, end - t);
            __syncthreads();
            if (tid < m) {
                int s = seg * NP + t + tid;
                s_px[tid] = g_px[s];
                s_py[tid] = g_py[s];
                s_ux[tid] = g_ux[s];
                s_uy[tid] = g_uy[s];
                s_dd[tid] = g_dd[s];
            }
            if (tid == m) {              // sentinel pad (ok == false always)
                s_px[tid] = 0.f; s_py[tid] = 0.f;
                s_ux[tid] = 0.f; s_uy[tid] = 0.f;
                s_dd[tid] = 0.f;
            }
            __syncthreads();

            int mp = (m + 1) & ~1;       // even-padded count
            #pragma unroll 2
            for (int j = 0; j < mp; j += 2) {
                u64 npx = *(const u64*)(s_px + j);   // {-pxA, -pxB}
                u64 npy = *(const u64*)(s_py + j);
                u64 ux2 = *(const u64*)(s_ux + j);   // {2uxA, 2uxB}
                u64 uy2 = *(const u64*)(s_uy + j);
                float ddA = s_dd[j], ddB = s_dd[j + 1];

                u64 ddy = add2(byf2, npy);           // by - py
                u64 t2  = fma2(ddy, ddy, eps2);      // ddy^2 + eps
                u64 dyu = mul2(ddy, uy2);            // ddy * 2uy
                u64 ddx = add2(bx02, npx);           // bx0 - px

                #pragma unroll
                for (int b = 0; b < BPT; b++) {
                    u64 nxy = fma2(ddx, ddx, t2);    // ddx^2+ddy^2+eps  (>0)
                    u64 dot = fma2(ddx, ux2, dyu);   // 2*(ddx*ux+ddy*uy)
                    ddx = add2(ddx, eight2);
                    float nxyA, nxyB, dotA, dotB;
                    unpack2(nxy, nxyA, nxyB);
                    unpack2(dot, dotA, dotB);
                    float daA = dotA * fabsf(dotA);  // signed square
                    float daB = dotB * fabsf(dotB);
                    // dot>0 && dot^2>nxy  <=>  signed-int(da) > signed-int(nxy)
                    // (nxy > 0 strictly; IEEE totally ordered for these values)
                    int okA = __float_as_int(daA) > __float_as_int(nxyA);
                    int okB = __float_as_int(daB) > __float_as_int(nxyB);
                    cH[b] += okA;
                    cH[b] += okB;
                    aD[b] += okA ? ddA : 0.0f;
                    aD[b] += okB ? ddB : 0.0f;
                }
            }
        }

        if (active) {
            int binbase = binrow * BWID + colg * BPT;
            #pragma unroll
            for (int b = 0; b < BPT; b++) {
                if (cH[b] != 0) {
                    atomicAdd(&hough[(seg + 1) * NB + binbase + b], (float)cH[b]);
                    atomicAdd(&g_dsum[seg * NB + binbase + b], aD[b]);
                }
            }
        }
        __syncthreads();
    }

    // ---------- fused epilogue: last CTA does argmax + ROI math ----------
    __threadfence();
    __syncthreads();
    if (tid == 0) {
        int t = atomicAdd(&g_done, 1);
        s_last = (t == TOTAL_CTAS - 1);
    }
    __syncthreads();
    if (!s_last) return;
    __threadfence();   // acquire: all other CTAs' atomics now visible via L2

    for (int c = 0; c < NC; c++) {
        int peak; float votes;
        if (c == 0) {            // class-0 hough row is identically zero
            peak = 0; votes = 0.0f;
        } else {
            float best = -1.0f; int bi = 0;
            #pragma unroll
            for (int k = 0; k < 19; k++) {
                int i = tid + k * 256;
                float v = (i < NB) ? __ldcg(&hough[c * NB + i]) : -2.0f;
                if (v > best) { best = v; bi = i; }
            }
            sv[tid] = best; si[tid] = bi;
            __syncthreads();
            #pragma unroll
            for (int s = 128; s > 0; s >>= 1) {
                if (tid < s) {
                    float v2 = sv[tid + s]; int i2 = si[tid + s];
                    if (v2 > sv[tid] || (v2 == sv[tid] && i2 < si[tid])) {
                        sv[tid] = v2; si[tid] = i2;
                    }
                }
                __syncthreads();
            }
            peak = si[0]; votes = sv[0];
        }

        if (tid == 0) {
            float ds    = (c > 0) ? __ldcg(&g_dsum[(c - 1) * NB + peak]) : 0.0f;
            float depth = ds / fmaxf(votes, 1.0f);
            float cx = 4.0f + 8.0f * (float)(peak % BWID);
            float cy = 4.0f + 8.0f * (float)(peak / BWID);
            float cnt = (float)g_cnt[c];
            float score = votes / fmaxf(cnt, 1.0f);
            bool  valid = (cnt > 5.0f) && (score > 0.3f);
            float fx = meta[0], fy = meta[4];
            float e0 = extents[c*3+0], e1 = extents[c*3+1], e2 = extents[c*3+2];
            float diag = sqrtf(e0*e0 + e1*e1 + e2*e2);
            float sz = fmaxf(fabsf(depth), 0.001f);
            float bw = fabsf(diag * fx) / sz;
            float bh = fabsf(diag * fy) / sz;
            rois[c*6+0] = (float)c;
            rois[c*6+1] = cx - bw * 0.5f;
            rois[c*6+2] = cy - bh * 0.5f;
            rois[c*6+3] = cx + bw * 0.5f;
            rois[c*6+4] = cy + bh * 0.5f;
            rois[c*6+5] = valid ? score : 0.0f;
        }
        __syncthreads();
    }

    // reset counters for the next graph replay
    if (tid < 2)  g_n[tid] = 0;
    if (tid < NC) g_cnt[tid] = 0;
    if (tid == 0) g_done = 0;
}

extern "C" void kernel_launch(void* const* d_in, const int* in_sizes, int n_in,
                              void* d_out, int out_size) {
    const int*   label = (const int*)  d_in[0];
    const float* vert  = (const float*)d_in[1];
    const float* meta  = (const float*)d_in[2];
    const float* ext   = (const float*)d_in[3];
    float* out = (float*)d_out;

    // Output is the flattened tuple (rois[3,6], hough[3,4800]) -> 18 + 14400.
    float *rois_p, *hough_p;
    if (out_size >= NC*6 + NC*NB) {
        rois_p = out; hough_p = out + NC*6;
    } else if (out_size >= NC*NB) {
        void* tmp = nullptr;
        cudaGetSymbolAddress(&tmp, g_rois_scratch);
        rois_p = (float*)tmp; hough_p = out;
    } else {
        void* tmp = nullptr;
        cudaGetSymbolAddress(&tmp, g_hough_scratch);
        rois_p = out; hough_p = (float*)tmp;
    }

    prep_k<<<(PREP_TH + 255) / 256, 256>>>(label, vert, hough_p);
    dim3 vgrid(BGRID, PSPLIT);
    vote_k<<<vgrid, 256>>>(hough_p, rois_p, meta, ext);
}